// round 2
// baseline (speedup 1.0000x reference)
#include <cuda_runtime.h>
#include <cuda_bf16.h>

// Problem constants (fixed shapes from reference)
constexpr int B = 256;
constexpr int P = 1024;
constexpr int G = 128;
constexpr float DIST_T2 = 500.0f * 500.0f;   // compare squared distance
constexpr float BBOX_THRESH = 0.1f;

constexpr int THREADS = 128;
constexpr int IPROP   = 4;                    // proposals per thread
constexpr int PROPS_PER_CTA = THREADS * IPROP; // 512

__global__ __launch_bounds__(THREADS, 8) void proposal_kernel(
    const float* __restrict__ topk_index,    // [B,P,3]
    const float* __restrict__ topk_confs,    // [B,P]
    const float* __restrict__ bbox_preds,    // [B,P,2]
    const float* __restrict__ gt_3d,         // [B,G,3]
    const float* __restrict__ gt_bbox,       // [B,G,2]
    const int*   __restrict__ num_person,    // [B]
    float*       __restrict__ out)           // [B,P,7]
{
    __shared__ float4 sgt[G];      // (gx, gy, gz, unused) -> one LDS.128 per GT
    __shared__ float  sb0[G], sb1[G];

    const int b   = blockIdx.y;
    const int tid = threadIdx.x;

    // Stage this batch's GT data into shared memory (128 threads, 128 slots).
    {
        const float* g3 = gt_3d + ((size_t)b * G + tid) * 3;
        sgt[tid] = make_float4(g3[0], g3[1], g3[2], 0.0f);
        const float* gb = gt_bbox + ((size_t)b * G + tid) * 2;
        sb0[tid] = gb[0];
        sb1[tid] = gb[1];
    }
    const int n = num_person[b];   // uniform per CTA -> zero divergence
    __syncthreads();

    // 4 proposals per thread, coalesced: p_i = base + i*THREADS + tid
    const int pbase = blockIdx.x * PROPS_PER_CTA + tid;

    float x[IPROP], y[IPROP], z[IPROP];
    float best[IPROP];
    int   bg[IPROP];

    #pragma unroll
    for (int i = 0; i < IPROP; ++i) {
        const size_t bp = (size_t)b * P + pbase + i * THREADS;
        x[i] = topk_index[bp * 3 + 0];
        y[i] = topk_index[bp * 3 + 1];
        z[i] = topk_index[bp * 3 + 2];
        best[i] = 3.402823466e38f;
        bg[i]   = 0;
    }

    // Argmin over valid GT slots; strict < keeps first-index tie-break
    // (JAX argmin). One LDS.128 serves 4 independent distance chains.
    #pragma unroll 2
    for (int g = 0; g < n; ++g) {
        const float4 gt = sgt[g];
        #pragma unroll
        for (int i = 0; i < IPROP; ++i) {
            const float dx = x[i] - gt.x;
            const float dy = y[i] - gt.y;
            const float dz = z[i] - gt.z;
            const float d2 = fmaf(dx, dx, fmaf(dy, dy, dz * dz));
            if (d2 < best[i]) { best[i] = d2; bg[i] = g; }
        }
    }

    #pragma unroll
    for (int i = 0; i < IPROP; ++i) {
        const size_t bp = (size_t)b * P + pbase + i * THREADS;

        // dist > 500  <=>  d2 > 500^2 (sqrt monotone; compare-exact)
        const float p2g = (best[i] > DIST_T2) ? -1.0f : (float)bg[i];

        const float mb0 = sb0[bg[i]];
        const float mb1 = sb1[bg[i]];
        const float q0  = bbox_preds[bp * 2 + 0];
        const float q1  = bbox_preds[bp * 2 + 1];

        const bool cond = (p2g >= 0.0f) &&
                          ((q0 < mb0 - BBOX_THRESH) || (q1 < mb1 - BBOX_THRESH));
        const float o5 = cond ? mb0 : q0;
        const float o6 = cond ? mb1 : q1;
        const float conf = topk_confs[bp];

        float* o = out + bp * 7;
        o[0] = x[i];
        o[1] = y[i];
        o[2] = z[i];
        o[3] = p2g;
        o[4] = conf;
        o[5] = o5;
        o[6] = o6;
    }
}

extern "C" void kernel_launch(void* const* d_in, const int* in_sizes, int n_in,
                              void* d_out, int out_size) {
    const float* topk_index  = (const float*)d_in[0];  // [B,P,3]
    const float* topk_confs  = (const float*)d_in[1];  // [B,P]
    const float* bbox_preds  = (const float*)d_in[2];  // [B,P,2]
    const float* gt_3d       = (const float*)d_in[3];  // [B,G,3]
    const float* gt_bbox     = (const float*)d_in[4];  // [B,G,2]
    const int*   num_person  = (const int*)  d_in[5];  // [B]
    float*       out         = (float*)d_out;          // [B,P,7]

    dim3 grid(P / PROPS_PER_CTA, B);
    proposal_kernel<<<grid, THREADS>>>(topk_index, topk_confs, bbox_preds,
                                       gt_3d, gt_bbox, num_person, out);
}

// round 3
// speedup vs baseline: 1.2786x; 1.2786x over previous
#include <cuda_runtime.h>
#include <cuda_bf16.h>

// Problem constants (fixed shapes from reference)
constexpr int B = 256;
constexpr int P = 1024;
constexpr int G = 128;
constexpr float DIST_T2 = 500.0f * 500.0f;   // compare squared distance
constexpr float BBOX_THRESH = 0.1f;

constexpr int THREADS = 128;
constexpr int IPROP   = 2;                     // proposals per thread
constexpr int PROPS_PER_CTA = THREADS * IPROP; // 256

__global__ __launch_bounds__(THREADS) void proposal_kernel(
    const float* __restrict__ topk_index,    // [B,P,3]
    const float* __restrict__ topk_confs,    // [B,P]
    const float* __restrict__ bbox_preds,    // [B,P,2]
    const float* __restrict__ gt_3d,         // [B,G,3]
    const float* __restrict__ gt_bbox,       // [B,G,2]
    const int*   __restrict__ num_person,    // [B]
    float*       __restrict__ out)           // [B,P,7]
{
    __shared__ float4 sgt[G];      // (gx, gy, gz, pad) -> one LDS.128 per GT
    __shared__ float  sb0[G], sb1[G];

    const int b   = blockIdx.y;
    const int tid = threadIdx.x;

    // Stage this batch's GT data into shared (128 threads <-> 128 slots).
    {
        const float* g3 = gt_3d + ((size_t)b * G + tid) * 3;
        sgt[tid] = make_float4(g3[0], g3[1], g3[2], 0.0f);
        const float* gb = gt_bbox + ((size_t)b * G + tid) * 2;
        sb0[tid] = gb[0];
        sb1[tid] = gb[1];
    }
    const int n = num_person[b];   // uniform per CTA -> zero divergence
    __syncthreads();

    // 2 proposals per thread, coalesced: p_i = base + i*THREADS + tid
    const int pbase = blockIdx.x * PROPS_PER_CTA + tid;

    float x[IPROP], y[IPROP], z[IPROP];
    float best[IPROP];
    int   bg[IPROP];

    #pragma unroll
    for (int i = 0; i < IPROP; ++i) {
        const size_t bp = (size_t)b * P + pbase + i * THREADS;
        x[i] = topk_index[bp * 3 + 0];
        y[i] = topk_index[bp * 3 + 1];
        z[i] = topk_index[bp * 3 + 2];
        best[i] = 3.402823466e38f;
        bg[i]   = 0;
    }

    // Argmin over valid GT slots; strict < keeps first-index tie-break
    // (JAX argmin). One LDS.128 serves 2 independent distance chains.
    #pragma unroll 4
    for (int g = 0; g < n; ++g) {
        const float4 gt = sgt[g];
        #pragma unroll
        for (int i = 0; i < IPROP; ++i) {
            const float dx = x[i] - gt.x;
            const float dy = y[i] - gt.y;
            const float dz = z[i] - gt.z;
            const float d2 = fmaf(dx, dx, fmaf(dy, dy, dz * dz));
            if (d2 < best[i]) { best[i] = d2; bg[i] = g; }
        }
    }

    #pragma unroll
    for (int i = 0; i < IPROP; ++i) {
        const size_t bp = (size_t)b * P + pbase + i * THREADS;

        // dist > 500  <=>  d2 > 500^2 (sqrt monotone; compare-exact)
        const float p2g = (best[i] > DIST_T2) ? -1.0f : (float)bg[i];

        const float mb0 = sb0[bg[i]];
        const float mb1 = sb1[bg[i]];
        const float q0  = bbox_preds[bp * 2 + 0];
        const float q1  = bbox_preds[bp * 2 + 1];

        const bool cond = (p2g >= 0.0f) &&
                          ((q0 < mb0 - BBOX_THRESH) || (q1 < mb1 - BBOX_THRESH));
        const float o5 = cond ? mb0 : q0;
        const float o6 = cond ? mb1 : q1;
        const float conf = topk_confs[bp];

        float* o = out + bp * 7;
        o[0] = x[i];
        o[1] = y[i];
        o[2] = z[i];
        o[3] = p2g;
        o[4] = conf;
        o[5] = o5;
        o[6] = o6;
    }
}

extern "C" void kernel_launch(void* const* d_in, const int* in_sizes, int n_in,
                              void* d_out, int out_size) {
    const float* topk_index  = (const float*)d_in[0];  // [B,P,3]
    const float* topk_confs  = (const float*)d_in[1];  // [B,P]
    const float* bbox_preds  = (const float*)d_in[2];  // [B,P,2]
    const float* gt_3d       = (const float*)d_in[3];  // [B,G,3]
    const float* gt_bbox     = (const float*)d_in[4];  // [B,G,2]
    const int*   num_person  = (const int*)  d_in[5];  // [B]
    float*       out         = (float*)d_out;          // [B,P,7]

    dim3 grid(P / PROPS_PER_CTA, B);
    proposal_kernel<<<grid, THREADS>>>(topk_index, topk_confs, bbox_preds,
                                       gt_3d, gt_bbox, num_person, out);
}